// round 9
// baseline (speedup 1.0000x reference)
#include <cuda_runtime.h>
#include <cstdint>

// ARIMA(2,1,2) eps recursion, B=1024, L=65536.
// eps_t = y[t+3] - (1+phi0)*y[t+2] - phi1*y[t+1] - mu - th0*eps_{t-1} - th1*eps_{t-2}
// Chunk-parallel (37 chunks/row, 64-step warm-up, IIR state decays ~rho^64).
// 256 compute threads + 256 IO threads per block (warp-specialized):
//   compute: 64-step tiles from swizzled smem (4x16-step sub-blocks, 1-FMA chain)
//   IO:      store eps of tile k + cp.async-refill window k+3, overlapped with
//            compute of tile k+1. Named barriers 1 ("window ready") and
//            2 ("eps ready"); cp.async groups live only in IO threads.
// 256B contiguous gmem read granule per segment (2x R3) for DRAM row locality.

#define L_LEN   65536
#define N_OUT   65535
#define N_EPS   65533
#define BTH     512
#define NSEG    256          // segments per block (one per compute thread)
#define CPR     37           // chunks per row (37*1792 >= 65533)
#define CSZ     1792         // outputs per chunk
#define WUP     64           // warm-up steps (1 tile)
#define TT      64           // steps per tile
#define NTILES  29           // (WUP+CSZ)/TT
#define NSTG    3            // ring stages
#define STAGE_B (NSEG*TT*4)  // 64KB per stage
#define STAGE_F4 (STAGE_B/16)
#define GRID    148          // 1024*37 / 256 segs == one block per SM, one wave

__device__ __forceinline__ uint32_t smem_u32(const void* p) {
    uint32_t a;
    asm("{ .reg .u64 t; cvta.to.shared.u64 t, %1; cvt.u32.u64 %0, t; }"
        : "=r"(a) : "l"(p));
    return a;
}

__global__ __launch_bounds__(BTH, 1)
void arima_eps_kernel(const float* __restrict__ y,
                      const float* __restrict__ phi,
                      const float* __restrict__ theta,
                      const float* __restrict__ mu,
                      float* __restrict__ out)
{
    extern __shared__ float smem[];              // 3 stages + segment table
    float4* stg  = (float4*)smem;
    int4*   sm_p = (int4*)(smem + NSTG * (STAGE_B / 4));

    const int tid = threadIdx.x;

    const float phi0 = phi[0];
    const float phi1 = phi[1];
    const float th0  = theta[0];
    const float th1  = theta[1];
    const float muv  = mu[0];
    const float c2   = 1.0f + phi0;

    // Per-segment params: .x = ybase + startT, .y = startT,
    // .z = out row base + startT, .w = ybase (safe fallback address)
    if (tid < NSEG) {
        int cid = blockIdx.x * NSEG + tid;
        int row = cid / CPR;
        int cno = cid - row * CPR;
        int4 p;
        p.y = cno * CSZ - WUP;
        p.x = row * L_LEN + p.y;
        p.z = row * N_OUT + p.y;
        p.w = row * L_LEN;
        sm_p[tid] = p;
    }
    __syncthreads();

    if (tid < NSEG) {
        // ================= COMPUTE role =================
        const int s  = tid;
        const int f7 = s & 7;
        const int myStart = sm_p[s].y;
        float e1 = 0.f, e2 = 0.f, yc1 = 0.f, yc2 = 0.f;

        for (int k = 0; k < NTILES; ++k) {
            asm volatile("bar.sync 1, %0;" :: "n"(BTH) : "memory");

            const float4* rowA = stg + (size_t)(k % NSTG) * STAGE_F4 + s * 16;
            const float4* rowB = stg + (size_t)((k + 1) % NSTG) * STAGE_F4 + s * 16;
            float4* rowW = (float4*)rowA;

            if (myStart + k * TT == 0) { e1 = 0.f; e2 = 0.f; }

            #pragma unroll
            for (int b = 0; b < 4; ++b) {
                // v[0..15] = y[local 16b .. 16b+15], v[16..18] = peek
                float v[19];
                {
                    #pragma unroll
                    for (int c = 0; c < 4; ++c) {
                        int cc = 4 * b + c;
                        float4 q = rowA[((cc & 7) ^ f7) | (cc & 8)];
                        v[c*4+0] = q.x; v[c*4+1] = q.y;
                        v[c*4+2] = q.z; v[c*4+3] = q.w;
                    }
                    float4 pk;
                    if (b < 3) {
                        int cc = 4 * b + 4;
                        pk = rowA[((cc & 7) ^ f7) | (cc & 8)];
                    } else {
                        pk = rowB[f7];            // next window, chunk 0
                    }
                    v[16] = pk.x; v[17] = pk.y; v[18] = pk.z;
                }

                #pragma unroll
                for (int e = 0; e < 16; ++e) {
                    float ynew = v[e + 3];                  // y[t+3]
                    float A = fmaf(-c2, yc2, ynew);
                    A = fmaf(-phi1, yc1, A) - muv;          // off-chain
                    float P  = fmaf(-th1, e2, A);           // uses 2-step-old eps
                    float ep = fmaf(-th0, e1, P);           // 1-FMA critical chain
                    e2 = e1; e1 = ep;
                    yc1 = yc2; yc2 = ynew;
                    v[e] = ep;                              // slot already consumed
                }

                // eps back in place (same swizzled slots)
                #pragma unroll
                for (int c = 0; c < 4; ++c) {
                    int cc = 4 * b + c;
                    rowW[((cc & 7) ^ f7) | (cc & 8)] =
                        make_float4(v[c*4+0], v[c*4+1], v[c*4+2], v[c*4+3]);
                }
            }
            asm volatile("bar.arrive 2, %0;" :: "n"(BTH) : "memory");
        }
    } else {
        // ================= IO role =================
        const int it_  = tid - NSEG;             // 0..255
        const int wio  = it_ >> 5;               // IO warp 0..7
        const int lane = it_ & 31;
        const uint32_t smem0 = smem_u32(smem);

        // cp.async mapping: thread covers chunk cch (16B) of segments
        // s = j*16 + s0, j = 0..15. Lanes 0-15 of a warp cover one segment's
        // 256B contiguously. Swizzled f4 slot: ((c&7)^(s&7)) | (c&8);
        // s&7 == s0&7 for all j.
        const int cch = it_ & 15;
        const int s0  = it_ >> 4;
        const int c4  = cch * 4;
        const uint32_t dst0 = (uint32_t)(s0 * 256 +
                            ((((cch & 7) ^ (s0 & 7)) | (cch & 8)) << 4));

        auto issue_window = [&](int m, int stage) {
            uint32_t dst = smem0 + (uint32_t)stage * STAGE_B + dst0;
            const int K = m * TT + c4;
            #pragma unroll
            for (int j = 0; j < 16; ++j) {
                int s = j * 16 + s0;
                int4 p = sm_p[s];
                int pos = p.y + K;
                bool ok = (unsigned)pos <= (unsigned)(L_LEN - 4);
                int so = ok ? (p.x + K) : p.w;
                int n  = ok ? 16 : 0;
                const float* src = y + so;
                asm volatile("cp.async.cg.shared.global [%0], [%1], 16, %2;\n"
                             :: "r"(dst), "l"(src), "r"(n));
                dst += 16 * 256;
            }
            asm volatile("cp.async.commit_group;\n" ::: "memory");
        };

        // Prime: windows 0,1,2. Gate tile 0 on {w0 full, w1 head}.
        issue_window(0, 0);
        issue_window(1, 1);
        issue_window(2, 2);
        asm volatile("cp.async.wait_group 1;\n" ::: "memory");   // w0,w1 done
        asm volatile("bar.arrive 1, %0;" :: "n"(BTH) : "memory");

        for (int k = 0; k < NTILES; ++k) {
            // wait "eps of tile k ready" from compute
            asm volatile("bar.sync 2, %0;" :: "n"(BTH) : "memory");

            // ---- store eps_k (coalesced 128B warp ops, 8 IO warps) ----
            if (k >= 1) {                          // tile 0 is pure warm-up
                const float* sf = smem + (size_t)(k % NSTG) * (STAGE_B / 4);
                const int koff = k * TT;
                #pragma unroll 4
                for (int j = 0; j < 64; ++j) {
                    int op = j * 8 + wio;          // warp-uniform
                    int s  = op >> 1;
                    int h  = op & 1;               // which 128B half of 256B
                    int4 p = sm_p[s];
                    int word = s * 64 +
                        ((((lane >> 2) ^ (s & 7)) | (h << 3)) << 2) + (lane & 3);
                    int tb = p.y + koff + h * 32;  // t for lane 0
                    if (tb + 31 < N_EPS) {
                        out[p.z + koff + h * 32 + lane] = sf[word];
                    } else {
                        int t = tb + lane;
                        if (t < N_OUT)
                            out[p.z + koff + h * 32 + lane] =
                                (t < N_EPS) ? sf[word] : 0.0f;
                    }
                }
            }

            // ---- refill stage k%3 with window k+3 (windows 0..NTILES used) ----
            if (k + NSTG <= NTILES) {
                issue_window(k + NSTG, k % NSTG);
            } else {
                asm volatile("cp.async.commit_group;\n" ::: "memory");
            }
            // ensure window k+2 fully resident (k+3 may stay pending)
            asm volatile("cp.async.wait_group 1;\n" ::: "memory");
            if (k < NTILES - 1)
                asm volatile("bar.arrive 1, %0;" :: "n"(BTH) : "memory");
        }
    }
}

extern "C" void kernel_launch(void* const* d_in, const int* in_sizes, int n_in,
                              void* d_out, int out_size) {
    const float* y     = (const float*)d_in[0];
    const float* phi   = (const float*)d_in[1];
    const float* theta = (const float*)d_in[2];
    const float* mu    = (const float*)d_in[3];
    float* out = (float*)d_out;

    size_t smem_bytes = (size_t)NSTG * STAGE_B + NSEG * sizeof(int4);
    cudaFuncSetAttribute(arima_eps_kernel,
                         cudaFuncAttributeMaxDynamicSharedMemorySize,
                         (int)smem_bytes);
    arima_eps_kernel<<<GRID, BTH, smem_bytes>>>(y, phi, theta, mu, out);
}

// round 10
// speedup vs baseline: 1.4461x; 1.4461x over previous
#include <cuda_runtime.h>
#include <cstdint>

// ARIMA(2,1,2) eps recursion, B=1024, L=65536.
// eps_t = y[t+3] - (1+phi0)*y[t+2] - phi1*y[t+1] - mu - th0*eps_{t-1} - th1*eps_{t-2}
// Chunk-parallel (37 chunks/row, 64-step warm-up, IIR state decays ~rho^64).
// TT=64 -> 256B contiguous DRAM read granule per segment (vs 128B in the
// 130.6us baseline) to test the DRAM-row-locality ceiling with a LEAN SM side:
//   - padded 272B smem rows (no XOR swizzle anywhere, all addressing affine)
//   - warp-specialized: 256 compute threads (16-step sub-blocks, ~60 regs)
//     + 256 IO threads (cp.async refill + slim store loop, int2 table)
//   - named barriers 1 ("window ready") / 2 ("eps ready")

#define L_LEN   65536
#define N_OUT   65535
#define N_EPS   65533
#define BTH     512
#define NSEG    256          // segments per block (one per compute thread)
#define CPR     37           // chunks per row (37*1792 >= 65533)
#define CSZ     1792         // outputs per chunk
#define WUP     64           // warm-up steps (1 tile)
#define TT      64           // steps per tile
#define NTILES  29           // (WUP+CSZ)/TT
#define NSTG    3            // ring stages
#define ROWW    68           // words per segment row (64 data + 4 pad), 272B
#define STAGE_W (NSEG*ROWW)  // 17408 words per stage
#define STAGE_B (STAGE_W*4)  // 69632 bytes per stage
#define GRID    148          // 1024*37/256 == one block per SM, one wave

__device__ __forceinline__ uint32_t smem_u32(const void* p) {
    uint32_t a;
    asm("{ .reg .u64 t; cvta.to.shared.u64 t, %1; cvt.u32.u64 %0, t; }"
        : "=r"(a) : "l"(p));
    return a;
}

__global__ __launch_bounds__(BTH, 1)
void arima_eps_kernel(const float* __restrict__ y,
                      const float* __restrict__ phi,
                      const float* __restrict__ theta,
                      const float* __restrict__ mu,
                      float* __restrict__ out)
{
    extern __shared__ float smem[];              // 3 stages + tables
    int4* sm_p = (int4*)(smem + NSTG * STAGE_W);           // issue table
    int2* sm_q = (int2*)(smem + NSTG * STAGE_W + NSEG * 4); // store table

    const int tid = threadIdx.x;

    const float phi0 = phi[0];
    const float phi1 = phi[1];
    const float th0  = theta[0];
    const float th1  = theta[1];
    const float muv  = mu[0];
    const float c2   = 1.0f + phi0;

    // Tables. sm_p: .x = ybase+startT, .y = startT, .w = ybase (safe addr).
    //         sm_q: .x = outbase+startT, .y = startT.
    if (tid < NSEG) {
        int cid = blockIdx.x * NSEG + tid;
        int row = cid / CPR;
        int cno = cid - row * CPR;
        int4 p;
        p.y = cno * CSZ - WUP;
        p.x = row * L_LEN + p.y;
        p.z = 0;
        p.w = row * L_LEN;
        sm_p[tid] = p;
        int2 q;
        q.x = row * N_OUT + p.y;
        q.y = p.y;
        sm_q[tid] = q;
    }
    __syncthreads();

    if (tid < NSEG) {
        // ================= COMPUTE role (warps 0-7) =================
        const int s = tid;
        const int myStart = sm_p[s].y;
        float e1 = 0.f, e2 = 0.f, yc1 = 0.f, yc2 = 0.f;

        for (int k = 0; k < NTILES; ++k) {
            asm volatile("bar.sync 1, %0;" :: "n"(BTH) : "memory");

            float4* raA = (float4*)(smem + (size_t)(k % NSTG) * STAGE_W
                                         + s * ROWW);
            const float4* raB = (const float4*)(smem
                               + (size_t)((k + 1) % NSTG) * STAGE_W + s * ROWW);

            if (myStart + k * TT == 0) { e1 = 0.f; e2 = 0.f; }

            #pragma unroll
            for (int b = 0; b < 4; ++b) {
                // v[0..15] = y[16b .. 16b+15] local, v[16..18] = peek
                float v[19];
                #pragma unroll
                for (int c = 0; c < 4; ++c) {
                    float4 q = raA[4 * b + c];
                    v[c*4+0] = q.x; v[c*4+1] = q.y;
                    v[c*4+2] = q.z; v[c*4+3] = q.w;
                }
                {
                    float4 pk = (b < 3) ? raA[4 * b + 4] : raB[0];
                    v[16] = pk.x; v[17] = pk.y; v[18] = pk.z;
                }

                #pragma unroll
                for (int e = 0; e < 16; ++e) {
                    float ynew = v[e + 3];                  // y[t+3]
                    float A = fmaf(-c2, yc2, ynew);
                    A = fmaf(-phi1, yc1, A) - muv;          // off-chain
                    float P  = fmaf(-th1, e2, A);           // 2-step-old eps
                    float ep = fmaf(-th0, e1, P);           // 1-FMA chain
                    e2 = e1; e1 = ep;
                    yc1 = yc2; yc2 = ynew;
                    v[e] = ep;                              // slot consumed
                }

                #pragma unroll
                for (int c = 0; c < 4; ++c)
                    raA[4 * b + c] =
                        make_float4(v[c*4+0], v[c*4+1], v[c*4+2], v[c*4+3]);
            }
            asm volatile("bar.arrive 2, %0;" :: "n"(BTH) : "memory");
        }
    } else {
        // ================= IO role (warps 8-15) =================
        const int it_  = tid - NSEG;             // 0..255
        const int wio  = it_ >> 5;               // IO warp 0..7
        const int lane = it_ & 31;
        const uint32_t smem0 = smem_u32(smem);

        // cp.async mapping: thread owns 16B chunk cch of segments
        // s = j*16 + s0, j = 0..15 (lanes 0-15 cover one segment's 256B).
        const int cch = it_ & 15;
        const int s0  = it_ >> 4;
        const int cK  = cch * 4;                 // element offset of chunk
        const uint32_t dst0 = (uint32_t)(s0 * (ROWW * 4) + cch * 16);

        auto issue_window = [&](int m, int stage) {
            uint32_t dst = smem0 + (uint32_t)stage * STAGE_B + dst0;
            const int K = m * TT + cK;
            #pragma unroll
            for (int j = 0; j < 16; ++j) {
                int s = j * 16 + s0;
                int4 p = sm_p[s];
                int pos = p.y + K;
                bool ok = (unsigned)pos <= (unsigned)(L_LEN - 4);
                int so = ok ? (p.x + K) : p.w;
                int n  = ok ? 16 : 0;
                const float* src = y + so;
                asm volatile("cp.async.cg.shared.global [%0], [%1], 16, %2;\n"
                             :: "r"(dst), "l"(src), "r"(n));
                dst += 16 * (ROWW * 4);
            }
            asm volatile("cp.async.commit_group;\n" ::: "memory");
        };

        issue_window(0, 0);
        issue_window(1, 1);
        issue_window(2, 2);
        asm volatile("cp.async.wait_group 1;\n" ::: "memory"); // w0,w1 done
        asm volatile("bar.arrive 1, %0;" :: "n"(BTH) : "memory");

        for (int k = 0; k < NTILES; ++k) {
            asm volatile("bar.sync 2, %0;" :: "n"(BTH) : "memory");

            // ---- store eps_k: warp wio owns segments wio*32..+31,
            //      2 coalesced 128B ops per segment ----
            if (k >= 1) {                          // tile 0 is pure warm-up
                const float* sf = smem + (size_t)(k % NSTG) * STAGE_W;
                const int koff = k * TT;
                const int sbase = wio * 32;
                #pragma unroll 8
                for (int ss = 0; ss < 32; ++ss) {
                    int s = sbase + ss;
                    int2 q = sm_q[s];
                    const float* row = sf + s * ROWW;
                    int ob = q.x + koff;           // out addr for local t=0
                    int tb = q.y + koff;           // global t for local t=0
                    #pragma unroll
                    for (int h = 0; h < 2; ++h) {
                        float val = row[h * 32 + lane];
                        int tbh = tb + h * 32;
                        if (tbh + 31 < N_EPS) {
                            out[ob + h * 32 + lane] = val;
                        } else {
                            int t = tbh + lane;
                            if (t < N_OUT)
                                out[ob + h * 32 + lane] =
                                    (t < N_EPS) ? val : 0.0f;
                        }
                    }
                }
            }

            // ---- refill stage k%3 with window k+3 (windows 0..29 used) ----
            if (k + NSTG <= NTILES) {
                issue_window(k + NSTG, k % NSTG);
            } else {
                asm volatile("cp.async.commit_group;\n" ::: "memory");
            }
            // ensure window k+2 fully resident (k+3 may stay pending)
            asm volatile("cp.async.wait_group 1;\n" ::: "memory");
            if (k < NTILES - 1)
                asm volatile("bar.arrive 1, %0;" :: "n"(BTH) : "memory");
        }
    }
}

extern "C" void kernel_launch(void* const* d_in, const int* in_sizes, int n_in,
                              void* d_out, int out_size) {
    const float* y     = (const float*)d_in[0];
    const float* phi   = (const float*)d_in[1];
    const float* theta = (const float*)d_in[2];
    const float* mu    = (const float*)d_in[3];
    float* out = (float*)d_out;

    size_t smem_bytes = (size_t)NSTG * STAGE_B
                      + NSEG * sizeof(int4) + NSEG * sizeof(int2);
    cudaFuncSetAttribute(arima_eps_kernel,
                         cudaFuncAttributeMaxDynamicSharedMemorySize,
                         (int)smem_bytes);
    arima_eps_kernel<<<GRID, BTH, smem_bytes>>>(y, phi, theta, mu, out);
}

// round 11
// speedup vs baseline: 1.5888x; 1.0987x over previous
#include <cuda_runtime.h>
#include <cstdint>

// ARIMA(2,1,2) eps recursion, B=1024, L=65536.
// eps_t = y[t+3] - (1+phi0)*y[t+2] - phi1*y[t+1] - mu - th0*eps_{t-1} - th1*eps_{t-2}
// Chunk-parallel (18 chunks/row, 128-step warm-up, IIR state decays ~rho^128).
// TT=128 -> 512B contiguous DRAM granule per segment (R10 showed BW rises
// with granule: 128B->54%, 256B->61% of spec). Padded 528B smem rows (no
// swizzle, affine addressing). Warp-specialized: 128 compute + 256 IO threads.
// Named barriers 1 ("window ready") / 2 ("eps ready"). 3-stage cp.async ring.

#define L_LEN   65536
#define N_OUT   65535
#define N_EPS   65533
#define BTH     384
#define NCMP    128          // compute threads == segments per block
#define NSEG    128
#define CPR     18           // chunks per row (18*3712 >= 65533)
#define CSZ     3712         // outputs per chunk (29 tiles)
#define WUP     128          // warm-up steps (1 tile)
#define TT      128          // steps per tile
#define NTILES  30           // (WUP+CSZ)/TT
#define NSTG    3            // ring stages
#define ROWW    132          // words per segment row (128 data + 4 pad), 528B
#define STAGE_W (NSEG*ROWW)  // 16896 words per stage
#define STAGE_B (STAGE_W*4)  // 67584 bytes per stage
#define GRID    144          // 1024*18/128 == one wave

__device__ __forceinline__ uint32_t smem_u32(const void* p) {
    uint32_t a;
    asm("{ .reg .u64 t; cvta.to.shared.u64 t, %1; cvt.u32.u64 %0, t; }"
        : "=r"(a) : "l"(p));
    return a;
}

__global__ __launch_bounds__(BTH, 1)
void arima_eps_kernel(const float* __restrict__ y,
                      const float* __restrict__ phi,
                      const float* __restrict__ theta,
                      const float* __restrict__ mu,
                      float* __restrict__ out)
{
    extern __shared__ float smem[];              // 3 stages + tables
    int4* sm_p = (int4*)(smem + NSTG * STAGE_W);            // issue table
    int2* sm_q = (int2*)(smem + NSTG * STAGE_W + NSEG * 4); // store table

    const int tid = threadIdx.x;

    const float phi0 = phi[0];
    const float phi1 = phi[1];
    const float th0  = theta[0];
    const float th1  = theta[1];
    const float muv  = mu[0];
    const float c2   = 1.0f + phi0;

    // Tables. sm_p: .x = ybase+startT, .y = startT, .w = ybase (safe addr).
    //         sm_q: .x = outbase+startT, .y = startT.
    if (tid < NSEG) {
        int cid = blockIdx.x * NSEG + tid;
        int row = cid / CPR;
        int cno = cid - row * CPR;
        int4 p;
        p.y = cno * CSZ - WUP;
        p.x = row * L_LEN + p.y;
        p.z = 0;
        p.w = row * L_LEN;
        sm_p[tid] = p;
        int2 q;
        q.x = row * N_OUT + p.y;
        q.y = p.y;
        sm_q[tid] = q;
    }
    __syncthreads();

    if (tid < NCMP) {
        // ================= COMPUTE role (warps 0-3) =================
        const int s = tid;
        const int myStart = sm_p[s].y;
        float e1 = 0.f, e2 = 0.f, yc1 = 0.f, yc2 = 0.f;

        for (int k = 0; k < NTILES; ++k) {
            asm volatile("bar.sync 1, %0;" :: "n"(BTH) : "memory");

            float4* raA = (float4*)(smem + (size_t)(k % NSTG) * STAGE_W)
                        + s * (ROWW / 4);
            const float4* raB = (const float4*)(smem
                        + (size_t)((k + 1) % NSTG) * STAGE_W) + s * (ROWW / 4);

            if (myStart + k * TT == 0) { e1 = 0.f; e2 = 0.f; }

            #pragma unroll
            for (int b = 0; b < 8; ++b) {
                // v[0..15] = y[16b .. 16b+15] local, v[16..18] = peek
                float v[19];
                #pragma unroll
                for (int c = 0; c < 4; ++c) {
                    float4 q = raA[4 * b + c];
                    v[c*4+0] = q.x; v[c*4+1] = q.y;
                    v[c*4+2] = q.z; v[c*4+3] = q.w;
                }
                {
                    float4 pk = (b < 7) ? raA[4 * b + 4] : raB[0];
                    v[16] = pk.x; v[17] = pk.y; v[18] = pk.z;
                }

                #pragma unroll
                for (int e = 0; e < 16; ++e) {
                    float ynew = v[e + 3];                  // y[t+3]
                    float A = fmaf(-c2, yc2, ynew);
                    A = fmaf(-phi1, yc1, A) - muv;          // off-chain
                    float P  = fmaf(-th1, e2, A);           // 2-step-old eps
                    float ep = fmaf(-th0, e1, P);           // 1-FMA chain
                    e2 = e1; e1 = ep;
                    yc1 = yc2; yc2 = ynew;
                    v[e] = ep;                              // slot consumed
                }

                #pragma unroll
                for (int c = 0; c < 4; ++c)
                    raA[4 * b + c] =
                        make_float4(v[c*4+0], v[c*4+1], v[c*4+2], v[c*4+3]);
            }
            asm volatile("bar.arrive 2, %0;" :: "n"(BTH) : "memory");
        }
    } else {
        // ================= IO role (warps 4-11) =================
        const int it_  = tid - NCMP;             // 0..255
        const int wio  = it_ >> 5;               // IO warp 0..7
        const int lane = it_ & 31;
        const uint32_t smem0 = smem_u32(smem);

        // cp.async mapping: warp wio covers segments s = j*8 + wio, j=0..15;
        // lane owns 16B chunk `lane` -> each warp instruction is one fully
        // contiguous 512B gmem read into one segment row.
        const uint32_t dst0 = (uint32_t)(wio * (ROWW * 4) + lane * 16);
        const int cK = lane * 4;                 // element offset of chunk

        auto issue_window = [&](int m, int stage, bool headonly) {
            uint32_t dst = smem0 + (uint32_t)stage * STAGE_B + dst0;
            const int K = m * TT + cK;
            #pragma unroll
            for (int j = 0; j < 16; ++j) {
                int s = j * 8 + wio;
                int4 p = sm_p[s];
                int pos = p.y + K;
                bool ok = (unsigned)pos <= (unsigned)(L_LEN - 4);
                int so = ok ? (p.x + K) : p.w;
                int n  = ok ? 16 : 0;
                if (!headonly || lane == 0) {
                    const float* src = y + so;
                    asm volatile("cp.async.cg.shared.global [%0], [%1], 16, %2;\n"
                                 :: "r"(dst), "l"(src), "r"(n));
                }
                dst += 8 * (ROWW * 4);
            }
            asm volatile("cp.async.commit_group;\n" ::: "memory");
        };

        issue_window(0, 0, false);
        issue_window(1, 1, false);
        issue_window(2, 2, false);
        asm volatile("cp.async.wait_group 1;\n" ::: "memory"); // w0,w1 done
        asm volatile("bar.arrive 1, %0;" :: "n"(BTH) : "memory");

        for (int k = 0; k < NTILES; ++k) {
            asm volatile("bar.sync 2, %0;" :: "n"(BTH) : "memory");

            // ---- store eps_k: warp wio owns segments wio*16..+15,
            //      4 consecutive 128B ops per segment (512B contiguous) ----
            if (k >= 1) {                          // tile 0 is pure warm-up
                const float* sf = smem + (size_t)(k % NSTG) * STAGE_W;
                const int koff = k * TT;
                const int sbase = wio * 16;
                #pragma unroll 4
                for (int ss = 0; ss < 16; ++ss) {
                    int s = sbase + ss;
                    int2 q = sm_q[s];
                    const float* row = sf + s * ROWW;
                    int ob = q.x + koff;           // out addr for local t=0
                    int tb = q.y + koff;           // global t for local t=0
                    #pragma unroll
                    for (int h = 0; h < 4; ++h) {
                        float val = row[h * 32 + lane];
                        int tbh = tb + h * 32;
                        if (tbh + 31 < N_EPS) {
                            out[ob + h * 32 + lane] = val;
                        } else {
                            int t = tbh + lane;
                            if (t < N_OUT)
                                out[ob + h * 32 + lane] =
                                    (t < N_EPS) ? val : 0.0f;
                        }
                    }
                }
            }

            // ---- refill stage k%3 with window k+3 (windows 0..30 used;
            //      window 30 head-only: just the 16B peek per segment) ----
            if (k + NSTG <= NTILES) {
                issue_window(k + NSTG, k % NSTG, (k + NSTG) == NTILES);
            } else {
                asm volatile("cp.async.commit_group;\n" ::: "memory");
            }
            // ensure window k+2 fully resident (k+3 may stay pending)
            asm volatile("cp.async.wait_group 1;\n" ::: "memory");
            if (k < NTILES - 1)
                asm volatile("bar.arrive 1, %0;" :: "n"(BTH) : "memory");
        }
    }
}

extern "C" void kernel_launch(void* const* d_in, const int* in_sizes, int n_in,
                              void* d_out, int out_size) {
    const float* y     = (const float*)d_in[0];
    const float* phi   = (const float*)d_in[1];
    const float* theta = (const float*)d_in[2];
    const float* mu    = (const float*)d_in[3];
    float* out = (float*)d_out;

    size_t smem_bytes = (size_t)NSTG * STAGE_B
                      + NSEG * sizeof(int4) + NSEG * sizeof(int2);
    cudaFuncSetAttribute(arima_eps_kernel,
                         cudaFuncAttributeMaxDynamicSharedMemorySize,
                         (int)smem_bytes);
    arima_eps_kernel<<<GRID, BTH, smem_bytes>>>(y, phi, theta, mu, out);
}